// round 13
// baseline (speedup 1.0000x reference)
#include <cuda_runtime.h>
#include <cuda_fp16.h>
#include <cstdint>

// ---------------------------------------------------------------------------
// Problem constants (fixed by setup_inputs)
// ---------------------------------------------------------------------------
#define NN 250000
#define EE 1000000
#define BB 500
#define FD 78

// ---------------------------------------------------------------------------
// Scratch (device globals: no allocation allowed)
// ---------------------------------------------------------------------------
__device__ float    g_bufA[NN * 156];        // reused as fp16 (pitch 80/160)
__device__ float    g_bufB[NN * 156];
__device__ float    g_dinv[NN];
__device__ int      g_cnt[NN];
__device__ int      g_rowptr[NN + 1];
__device__ int      g_cursor[NN];
__device__ int      g_csrc[EE];
__device__ int      g_bsum[512];
__device__ int      g_boff[512];
__device__ unsigned g_pool[BB * 312];
__device__ float    g_S1[BB * 1024];
__device__ float    g_S2[BB * 512];
__device__ float    g_xc[BB * 256];
__device__ float    g_G[BB * 256 * 26];      // [b][o*8+k][l]
__device__ float    g_Cbuf[BB * 3872];
__device__ __half   g_W1h[78 * 80];          // W^T fp16, pitch-padded, pads zero
__device__ __half   g_W2h[156 * 80];
__device__ __half   g_W3h[312 * 160];

// ---------------------------------------------------------------------------
// mma / ldmatrix helpers (PTX ISA sm_80+, legal at compute_103)
// ---------------------------------------------------------------------------
__device__ __forceinline__ uint32_t smem_u32(const void* p) {
    uint32_t a;
    asm("{ .reg .u64 t; cvta.to.shared.u64 t, %1; cvt.u32.u64 %0, t; }" : "=r"(a) : "l"(p));
    return a;
}
__device__ __forceinline__ void ldm4(uint32_t* r, uint32_t addr) {
    asm volatile("ldmatrix.sync.aligned.m8n8.x4.shared.b16 {%0,%1,%2,%3}, [%4];"
        : "=r"(r[0]), "=r"(r[1]), "=r"(r[2]), "=r"(r[3]) : "r"(addr));
}
__device__ __forceinline__ void mma16816(float* c, const uint32_t* a, const uint32_t* b) {
    asm volatile(
        "mma.sync.aligned.m16n8k16.row.col.f32.f16.f16.f32 "
        "{%0,%1,%2,%3}, {%4,%5,%6,%7}, {%8,%9}, {%0,%1,%2,%3};"
        : "+f"(c[0]), "+f"(c[1]), "+f"(c[2]), "+f"(c[3])
        : "r"(a[0]), "r"(a[1]), "r"(a[2]), "r"(a[3]), "r"(b[0]), "r"(b[1]));
}

// ---------------------------------------------------------------------------
// Combined setup: zero cnt/pool/xc/S2 + fp16-transpose all three W matrices.
// ---------------------------------------------------------------------------
#define SETUP_N0 (NN)                 // cnt
#define SETUP_N1 (BB * 312)           // pool
#define SETUP_N2 (BB * 256)           // xc
#define SETUP_N3 (BB * 512)           // S2
#define SETUP_N4 (78 * 80)            // W1h
#define SETUP_N5 (156 * 80)           // W2h
#define SETUP_N6 (312 * 160)          // W3h
#define SETUP_TOT (SETUP_N0 + SETUP_N1 + SETUP_N2 + SETUP_N3 + SETUP_N4 + SETUP_N5 + SETUP_N6)

__global__ void k_setup(const float* __restrict__ W1, const float* __restrict__ W2,
                        const float* __restrict__ W3) {
    int i = blockIdx.x * blockDim.x + threadIdx.x;
    if (i < SETUP_N0) { g_cnt[i] = 0; return; }
    i -= SETUP_N0;
    if (i < SETUP_N1) { g_pool[i] = 0u; return; }
    i -= SETUP_N1;
    if (i < SETUP_N2) { g_xc[i] = 0.f; return; }
    i -= SETUP_N2;
    if (i < SETUP_N3) { g_S2[i] = 0.f; return; }
    i -= SETUP_N3;
    if (i < SETUP_N4) {
        int m = i / 80, k = i - m * 80;
        g_W1h[i] = __float2half((k < 78) ? W1[(size_t)k * 78 + m] : 0.f);
        return;
    }
    i -= SETUP_N4;
    if (i < SETUP_N5) {
        int m = i / 80, k = i - m * 80;
        g_W2h[i] = __float2half((k < 78) ? W2[(size_t)k * 156 + m] : 0.f);
        return;
    }
    i -= SETUP_N5;
    if (i < SETUP_N6) {
        int m = i / 160, k = i - m * 160;
        g_W3h[i] = __float2half((k < 156) ? W3[(size_t)k * 312 + m] : 0.f);
    }
}

// ---------------------------------------------------------------------------
// CSR build: count -> scan -> offsets -> fill
// ---------------------------------------------------------------------------
__global__ void k_count(const int* __restrict__ dst, int e) {
    int i = blockIdx.x * blockDim.x + threadIdx.x;
    if (i < e) atomicAdd(&g_cnt[dst[i]], 1);
}

__global__ void k_scan1(int n) {
    __shared__ int s[512];
    int t = threadIdx.x;
    int i = blockIdx.x * 512 + t;
    int v = (i < n) ? g_cnt[i] : 0;
    s[t] = v;
    __syncthreads();
    for (int off = 1; off < 512; off <<= 1) {
        int tmp = (t >= off) ? s[t - off] : 0;
        __syncthreads();
        s[t] += tmp;
        __syncthreads();
    }
    if (i < n) g_rowptr[i] = s[t] - v;
    if (t == 511) g_bsum[blockIdx.x] = s[511];
}

__global__ void k_scan2(int nb) {
    __shared__ int s[512];
    int t = threadIdx.x;
    int v = (t < nb) ? g_bsum[t] : 0;
    s[t] = v;
    __syncthreads();
    for (int off = 1; off < 512; off <<= 1) {
        int tmp = (t >= off) ? s[t - off] : 0;
        __syncthreads();
        s[t] += tmp;
        __syncthreads();
    }
    if (t < nb) g_boff[t] = s[t] - v;
}

__global__ void k_scan3(int n, int e) {
    int i = blockIdx.x * blockDim.x + threadIdx.x;
    if (i < n) {
        int v = g_rowptr[i] + g_boff[i >> 9];
        g_rowptr[i] = v;
        g_cursor[i] = v;
        g_dinv[i] = rsqrtf((float)g_cnt[i] + 1.0f);
    }
    if (i == 0) g_rowptr[n] = e;
}

__global__ void k_fill(const int* __restrict__ src, const int* __restrict__ dst, int e) {
    int i = blockIdx.x * blockDim.x + threadIdx.x;
    if (i < e) {
        int d = dst[i];
        int p = atomicAdd(&g_cursor[d], 1);
        g_csrc[p] = src[i];
    }
}

// ---------------------------------------------------------------------------
// Aggregation (one warp per node), fp16 prescaled input -> fp16 output.
//  AEPI 0: out = half( dv * acc )                           (plain Agg)
//  AEPI 1: out = half( dv * relu( dv * acc + bias[f] ) )    (layer-1 fused)
// Input rows carry their dinv factor already; pads (f2>=F2) written as zero.
// ---------------------------------------------------------------------------
template <int F2, int P2, int AEPI>
__global__ void k_agg_h(const __half2* __restrict__ in, __half2* __restrict__ out,
                        int n, const float* __restrict__ bias) {
    int warp = (blockIdx.x * blockDim.x + threadIdx.x) >> 5;
    int lane = threadIdx.x & 31;
    if (warp >= n) return;
    const int v = warp;
    constexpr int R = (F2 + 31) / 32;
    float dv = g_dinv[v];
    float2 acc[R];
#pragma unroll
    for (int i = 0; i < R; i++) {
        int f2 = lane + 32 * i;
        acc[i] = (f2 < F2) ? __half22float2(in[(size_t)v * P2 + f2]) : make_float2(0.f, 0.f);
    }
    int e0 = g_rowptr[v], e1 = g_rowptr[v + 1];
    for (int e = e0; e < e1; e++) {
        int u = g_csrc[e];
#pragma unroll
        for (int i = 0; i < R; i++) {
            int f2 = lane + 32 * i;
            if (f2 < F2) {
                float2 t = __half22float2(in[(size_t)u * P2 + f2]);
                acc[i].x += t.x;
                acc[i].y += t.y;
            }
        }
    }
#pragma unroll
    for (int i = 0; i < R; i++) {
        int f2 = lane + 32 * i;
        if (f2 < F2) {
            if (AEPI == 0) {
                out[(size_t)v * P2 + f2] = __floats2half2_rn(acc[i].x * dv, acc[i].y * dv);
            } else {
                float2 bb = *(const float2*)&bias[2 * f2];
                float ox = dv * fmaxf(acc[i].x * dv + bb.x, 0.f);
                float oy = dv * fmaxf(acc[i].y * dv + bb.y, 0.f);
                out[(size_t)v * P2 + f2] = __floats2half2_rn(ox, oy);
            }
        } else if (f2 < P2) {
            out[(size_t)v * P2 + f2] = __floats2half2_rn(0.f, 0.f);
        }
    }
}

// ---------------------------------------------------------------------------
// fp16 HMMA GEMM: C[node, feat] = X[node, :] @ Wt^T, fp32 accum.
// AF32=0: X fp16 pitch KTILE (pads zeroed), raw uint4 A-fill.
// AF32=1: X fp32 row length KINF (=78), converting A-fill (float2 -> half2).
// Wt fp16 [Mout][KTILE] pitch KTILE (pads zeroed). Block tile 128 x NT2*32.
// EPI 2: C = half(relu(acc+bias)*dinv[node])
// EPI 3: maxpool atomicMax into pool
// EPI 4: C = half(acc*dinv[node])                  (prescale-only, no bias)
// ---------------------------------------------------------------------------
template <int KTILE, int NT2, int EPI, int MINB, int AF32>
__global__ __launch_bounds__(256, MINB)
void k_hmma(const void* __restrict__ Xv,
            const __half* __restrict__ Wt, int Mout,
            __half* __restrict__ C, int ldc,
            int NR,
            const float* __restrict__ bias,
            const int* __restrict__ batch,
            unsigned* __restrict__ pool) {
    constexpr int PA = KTILE + 8;
    constexpr int KS = KTILE / 16;
    constexpr int CW = KTILE / 8;
    constexpr int BN = NT2 * 32;
    constexpr int NT = 2 * NT2;
    constexpr int KINF = 78;                // fp32 source row length (AF32 path)
    extern __shared__ __half sm[];
    __half* Asm = sm;                       // [128][PA]
    __half* Bsm = sm + 128 * PA;            // [BN][PA]

    const int tid = threadIdx.x;
    const int wid = tid >> 5;
    const int lane = tid & 31;
    const int n0 = blockIdx.x * BN;
    const int m0 = blockIdx.y * 128;
    const int wm = (wid & 3) * 32;
    const int wn = (wid >> 2) * (NT2 * 16);
    const int g = lane >> 2, tg = lane & 3;
    const int r8 = lane & 7, q = lane >> 3;

    if (AF32 == 0) {
        const __half* X = (const __half*)Xv;
#pragma unroll 4
        for (int idx = tid; idx < 128 * CW; idx += 256) {
            int row = idx / CW;
            int c = idx - row * CW;
            int node = m0 + row;
            uint4 v = make_uint4(0u, 0u, 0u, 0u);
            if (node < NR) v = *(const uint4*)&X[(size_t)node * KTILE + c * 8];
            *(uint4*)&Asm[row * PA + c * 8] = v;
        }
    } else {
        const float* X = (const float*)Xv;
        constexpr int H2 = KTILE / 2;       // half2 per row (40)
#pragma unroll 4
        for (int idx = tid; idx < 128 * H2; idx += 256) {
            int row = idx / H2;
            int j = idx - row * H2;
            int node = m0 + row;
            float2 v = make_float2(0.f, 0.f);
            if (node < NR && 2 * j + 1 < KINF)
                v = *(const float2*)&X[(size_t)node * KINF + 2 * j];
            *(__half2*)&Asm[row * PA + 2 * j] = __floats2half2_rn(v.x, v.y);
        }
    }
#pragma unroll 4
    for (int idx = tid; idx < BN * CW; idx += 256) {
        int row = idx / CW;
        int c = idx - row * CW;
        int feat = n0 + row;
        uint4 v = make_uint4(0u, 0u, 0u, 0u);
        if (feat < Mout) v = *(const uint4*)&Wt[(size_t)feat * KTILE + c * 8];
        *(uint4*)&Bsm[row * PA + c * 8] = v;
    }
    __syncthreads();

    const uint32_t sA = smem_u32(Asm);
    const uint32_t sB = smem_u32(Bsm);

    uint32_t aAddr[2], bAddr[NT2];
#pragma unroll
    for (int mt = 0; mt < 2; mt++)
        aAddr[mt] = sA + (uint32_t)((wm + mt * 16 + r8 + (q & 1) * 8) * PA + (q >> 1) * 8) * 2;
#pragma unroll
    for (int h = 0; h < NT2; h++)
        bAddr[h] = sB + (uint32_t)((wn + h * 16 + r8 + (q >> 1) * 8) * PA + (q & 1) * 8) * 2;

    float acc[2][NT][4];
#pragma unroll
    for (int mt = 0; mt < 2; mt++)
#pragma unroll
        for (int nt = 0; nt < NT; nt++)
#pragma unroll
            for (int i = 0; i < 4; i++) acc[mt][nt][i] = 0.f;

#pragma unroll
    for (int ks = 0; ks < KS; ks++) {
        uint32_t a[2][4], b[NT2][4];
        ldm4(a[0], aAddr[0] + ks * 32u);
        ldm4(a[1], aAddr[1] + ks * 32u);
#pragma unroll
        for (int h = 0; h < NT2; h++)
            ldm4(b[h], bAddr[h] + ks * 32u);
#pragma unroll
        for (int mt = 0; mt < 2; mt++)
#pragma unroll
            for (int nt = 0; nt < NT; nt++)
                mma16816(acc[mt][nt], a[mt], &b[nt >> 1][(nt & 1) * 2]);
    }

    if (EPI == 2 || EPI == 4) {
#pragma unroll
        for (int mt = 0; mt < 2; mt++) {
#pragma unroll
            for (int h = 0; h < 2; h++) {
                int node = m0 + wm + mt * 16 + g + h * 8;
                if (node >= NR) continue;
                float dv = g_dinv[node];
#pragma unroll
                for (int nt = 0; nt < NT; nt++) {
                    int feat = n0 + wn + nt * 8 + 2 * tg;
                    if (feat >= Mout) continue;
                    float ox, oy;
                    if (EPI == 2) {
                        ox = fmaxf(acc[mt][nt][h * 2 + 0] + bias[feat], 0.f) * dv;
                        oy = fmaxf(acc[mt][nt][h * 2 + 1] + bias[feat + 1], 0.f) * dv;
                    } else {
                        ox = acc[mt][nt][h * 2 + 0] * dv;
                        oy = acc[mt][nt][h * 2 + 1] * dv;
                    }
                    *(__half2*)&C[(size_t)node * ldc + feat] = __floats2half2_rn(ox, oy);
                }
            }
        }
    } else {
        int nodeA = m0 + wm + g;
        bool allv = (nodeA + 24) < NR;
        bool samegraph = allv && (batch[nodeA] == batch[nodeA + 24]);
        if (samegraph) {
            int bg = batch[nodeA];
#pragma unroll
            for (int nt = 0; nt < NT; nt++) {
                int feat = n0 + wn + nt * 8 + 2 * tg;
                if (feat >= Mout) continue;
#pragma unroll
                for (int e = 0; e < 2; e++) {
                    float m = fmaxf(fmaxf(acc[0][nt][e], acc[0][nt][2 + e]),
                                    fmaxf(acc[1][nt][e], acc[1][nt][2 + e]));
                    float v = fmaxf(m + bias[feat + e], 0.f);
                    if (v > 0.f)
                        atomicMax(&pool[(size_t)bg * 312 + feat + e], __float_as_uint(v));
                }
            }
        } else {
#pragma unroll
            for (int mt = 0; mt < 2; mt++) {
#pragma unroll
                for (int h = 0; h < 2; h++) {
                    int node = m0 + wm + mt * 16 + g + h * 8;
                    if (node >= NR) continue;
                    int bg = batch[node];
#pragma unroll
                    for (int nt = 0; nt < NT; nt++) {
                        int feat = n0 + wn + nt * 8 + 2 * tg;
                        if (feat >= Mout) continue;
#pragma unroll
                        for (int e = 0; e < 2; e++) {
                            float v = fmaxf(acc[mt][nt][h * 2 + e] + bias[feat + e], 0.f);
                            if (v > 0.f)
                                atomicMax(&pool[(size_t)bg * 312 + feat + e], __float_as_uint(v));
                        }
                    }
                }
            }
        }
    }
}

// ---------------------------------------------------------------------------
// Scalar f32 SIMT GEMM (small head GEMMs): C[NR,M] = A[NR,K] @ W[K,M]
// Epilogues: 0 STORE, 1 RELU, 4 ADD_ATOMIC (split-K, bias on z==0)
// ---------------------------------------------------------------------------
#define GBM 128
#define GBN 64
#define GBK 16

template <int EPI>
__global__ __launch_bounds__(256)
void k_gemm(const float* __restrict__ A, int lda,
            const float* __restrict__ W, int ldb,
            float* __restrict__ C, int ldc,
            int NR, int M, int K,
            const float* __restrict__ bias,
            int kChunk) {
    __shared__ float As[GBK][GBM + 4];
    __shared__ float Bs[GBK][GBN + 4];

    const int m0 = blockIdx.x * GBM;
    const int n0 = blockIdx.y * GBN;
    const int kb = blockIdx.z * kChunk;
    const int ke = min(K, kb + kChunk);

    const int tid = threadIdx.x;
    const int tN = tid & 15;
    const int tM = tid >> 4;

    float acc[8][4];
#pragma unroll
    for (int i = 0; i < 8; i++)
#pragma unroll
        for (int j = 0; j < 4; j++) acc[i][j] = 0.f;

    for (int k0 = kb; k0 < ke; k0 += GBK) {
#pragma unroll
        for (int r = 0; r < 8; r++) {
            int idx = tid + r * 256;
            int mm = idx >> 4, kk = idx & 15;
            int gm = m0 + mm, gk = k0 + kk;
            As[kk][mm] = (gm < NR && gk < ke) ? A[(size_t)gm * lda + gk] : 0.f;
        }
#pragma unroll
        for (int r = 0; r < 4; r++) {
            int idx = tid + r * 256;
            int kk = idx >> 6, nn = idx & 63;
            int gk = k0 + kk, gn = n0 + nn;
            Bs[kk][nn] = (gk < ke && gn < M) ? W[(size_t)gk * ldb + gn] : 0.f;
        }
        __syncthreads();
#pragma unroll
        for (int kk = 0; kk < GBK; kk++) {
            float4 a0 = *reinterpret_cast<const float4*>(&As[kk][tM * 8]);
            float4 a1 = *reinterpret_cast<const float4*>(&As[kk][tM * 8 + 4]);
            float4 b0 = *reinterpret_cast<const float4*>(&Bs[kk][tN * 4]);
            float a[8] = {a0.x, a0.y, a0.z, a0.w, a1.x, a1.y, a1.z, a1.w};
            float b[4] = {b0.x, b0.y, b0.z, b0.w};
#pragma unroll
            for (int i = 0; i < 8; i++)
#pragma unroll
                for (int j = 0; j < 4; j++)
                    acc[i][j] = fmaf(a[i], b[j], acc[i][j]);
        }
        __syncthreads();
    }

#pragma unroll
    for (int i = 0; i < 8; i++) {
        int row = m0 + tM * 8 + i;
        if (row >= NR) continue;
#pragma unroll
        for (int j = 0; j < 4; j++) {
            int col = n0 + tN * 4 + j;
            if (col >= M) continue;
            float v = acc[i][j];
            if (EPI == 0) {
                if (bias) v += bias[col];
                C[(size_t)row * ldc + col] = v;
            } else if (EPI == 1) {
                v += bias[col];
                C[(size_t)row * ldc + col] = fmaxf(v, 0.f);
            } else {  // 4
                if (blockIdx.z == 0 && bias) v += bias[col];
                atomicAdd(&C[(size_t)row * ldc + col], v);
            }
        }
    }
}

// ---------------------------------------------------------------------------
// Protein branch: G[b,o,k,l] = sum_i conv_w[o,i,k] * [target[b,i] == l]
// ---------------------------------------------------------------------------
__global__ void k_gbuild(const int* __restrict__ target, const float* __restrict__ conv_w) {
    __shared__ int   ts[1000];
    __shared__ float acc[256 * 26];
    const int b = blockIdx.x, tid = threadIdx.x;
    for (int i = tid; i < 1000; i += 256) ts[i] = target[b * 1000 + i];
#pragma unroll
    for (int l = 0; l < 26; l++) acc[tid * 26 + l] = 0.f;
    __syncthreads();
    const int o = tid >> 3, k = tid & 7;
    const float* wp = conv_w + o * 8000 + k;
    for (int i = 0; i < 1000; i++) {
        acc[tid * 26 + ts[i]] += wp[i * 8];
    }
    float* g = g_G + (size_t)b * 6656 + tid * 26;
#pragma unroll
    for (int l = 0; l < 26; l++) g[l] = acc[tid * 26 + l];
}

// c[b,o,h] = conv_b[o] + sum_{k,l} G[b,o,k,l] * emb[l, h+k]
__global__ void k_cconv(const float* __restrict__ emb, const float* __restrict__ conv_b) {
    __shared__ float Gs[8 * 26 * 33];   // [k][l][o+pad]
    __shared__ float Es[26 * 144];
    const int b = blockIdx.x, tid = threadIdx.x;
    for (int i = tid; i < 6656; i += 256) {
        int o = i / 208;
        int r = i - o * 208;
        int k = r / 26;
        int l = r - k * 26;
        Gs[(k * 26 + l) * 33 + o] = g_G[(size_t)b * 6656 + i];
    }
    for (int i = tid; i < 26 * 144; i += 256) {
        int l = i / 144;
        int c = i - l * 144;
        Es[i] = (c < 128) ? emb[l * 128 + c] : 0.f;
    }
    __syncthreads();

#pragma unroll
    for (int t2 = 0; t2 < 2; t2++) {
        int task = tid + t2 * 256;        // 512 tasks = 16 hg x 32 o
        int o = task & 31;
        int hg = task >> 5;
        int h0 = hg * 8;
        float cb = conv_b[o];
        float acc[8];
#pragma unroll
        for (int j = 0; j < 8; j++) acc[j] = cb;
        for (int l = 0; l < 26; l++) {
            float e[15];
#pragma unroll
            for (int t = 0; t < 15; t++) e[t] = Es[l * 144 + h0 + t];
#pragma unroll
            for (int k = 0; k < 8; k++) {
                float gv = Gs[(k * 26 + l) * 33 + o];
#pragma unroll
                for (int j = 0; j < 8; j++)
                    acc[j] = fmaf(gv, e[j + k], acc[j]);
            }
        }
#pragma unroll
        for (int j = 0; j < 8; j++) {
            int h = h0 + j;
            if (h < 121) g_Cbuf[(size_t)b * 3872 + o * 121 + h] = acc[j];
        }
    }
}

// ---------------------------------------------------------------------------
// Final projection: out[r] = dot(relu(S2[r,:512]), out_w) + out_b.
// ---------------------------------------------------------------------------
__global__ void k_out(const float* __restrict__ ow, const float* __restrict__ ob,
                      float* __restrict__ out, int rows) {
    int row = blockIdx.x * 8 + (threadIdx.x >> 5);
    int lane = threadIdx.x & 31;
    if (row >= rows) return;
    float s = 0.f;
    for (int j = lane; j < 512; j += 32) s += fmaxf(g_S2[row * 512 + j], 0.f) * ow[j];
#pragma unroll
    for (int off = 16; off; off >>= 1) s += __shfl_down_sync(0xffffffffu, s, off);
    if (lane == 0) out[row] = s + ob[0];
}

// ---------------------------------------------------------------------------
// Launch
// ---------------------------------------------------------------------------
extern "C" void kernel_launch(void* const* d_in, const int* in_sizes, int n_in,
                              void* d_out, int out_size) {
    const float* x       = (const float*)d_in[0];
    const int*   ei      = (const int*)d_in[1];
    const int*   batch   = (const int*)d_in[2];
    const int*   target  = (const int*)d_in[3];
    const float* W1      = (const float*)d_in[4];
    const float* b1      = (const float*)d_in[5];
    const float* W2      = (const float*)d_in[6];
    const float* b2      = (const float*)d_in[7];
    const float* W3      = (const float*)d_in[8];
    const float* b3      = (const float*)d_in[9];
    const float* fcg1_w  = (const float*)d_in[10];
    const float* fcg1_b  = (const float*)d_in[11];
    const float* fcg2_w  = (const float*)d_in[12];
    const float* fcg2_b  = (const float*)d_in[13];
    const float* emb     = (const float*)d_in[14];
    const float* conv_w  = (const float*)d_in[15];
    const float* conv_b  = (const float*)d_in[16];
    const float* fcxt_w  = (const float*)d_in[17];
    const float* fcxt_b  = (const float*)d_in[18];
    const float* fc1_w   = (const float*)d_in[19];
    const float* fc1_b   = (const float*)d_in[20];
    const float* fc2_w   = (const float*)d_in[21];
    const float* fc2_b   = (const float*)d_in[22];
    const float* out_w   = (const float*)d_in[23];
    const float* out_b   = (const float*)d_in[24];
    float* out = (float*)d_out;

    float *bufA, *bufB, *S1, *S2, *xc, *Cbuf;
    __half *w1h, *w2h, *w3h;
    unsigned* pool;
    cudaGetSymbolAddress((void**)&bufA, g_bufA);
    cudaGetSymbolAddress((void**)&bufB, g_bufB);
    cudaGetSymbolAddress((void**)&pool, g_pool);
    cudaGetSymbolAddress((void**)&S1,   g_S1);
    cudaGetSymbolAddress((void**)&S2,   g_S2);
    cudaGetSymbolAddress((void**)&xc,   g_xc);
    cudaGetSymbolAddress((void**)&Cbuf, g_Cbuf);
    cudaGetSymbolAddress((void**)&w1h,  g_W1h);
    cudaGetSymbolAddress((void**)&w2h,  g_W2h);
    cudaGetSymbolAddress((void**)&w3h,  g_W3h);

    __half* hA = (__half*)bufA;
    __half* hB = (__half*)bufB;

    const int N = NN, E = EE, B = BB;
    const int NB = (N + 511) / 512;
    const int MH = (N + 127) / 128;

    const int SM1 = (128 + 96) * 88 * 2;          // 39424 (KTILE=80,  BN=96)
    const int SM2 = (128 + 160) * 88 * 2;         // 50688 (KTILE=80,  BN=160)
    const int SM3 = (128 + 160) * 168 * 2;        // 96768 (KTILE=160, BN=160)
    cudaFuncSetAttribute(k_hmma<80, 3, 4, 2, 1>,  cudaFuncAttributeMaxDynamicSharedMemorySize, SM1);
    cudaFuncSetAttribute(k_hmma<80, 5, 2, 2, 0>,  cudaFuncAttributeMaxDynamicSharedMemorySize, SM2);
    cudaFuncSetAttribute(k_hmma<160, 5, 3, 2, 0>, cudaFuncAttributeMaxDynamicSharedMemorySize, SM3);

    // ---- combined setup (zeros + W-preps) ----
    k_setup<<<(SETUP_TOT + 255) / 256, 256>>>(W1, W2, W3);

    // ---- CSR + dinv ----
    k_count<<<(E + 255) / 256, 256>>>(ei + E, E);
    k_scan1<<<NB, 512>>>(N);
    k_scan2<<<1, 512>>>(NB);
    k_scan3<<<(N + 255) / 256, 256>>>(N, E);
    k_fill<<<(E + 255) / 256, 256>>>(ei, ei + E, E);

    // ---- GCN layers (layer 1 = GEMM-then-aggregate: no fp32 gather) ----
    // GEMM1': hB = dinv * (x @ W1)   [fp32 x read dense, fp16 out, pitch 80]
    k_hmma<80, 3, 4, 2, 1><<<dim3(1, MH), 256, SM1>>>(x, w1h, 78, hB, 80, N,
                                                      nullptr, nullptr, nullptr);
    // agg + fused relu/bias: hA = dinv * relu(Agg(x@W1) + b1)  (prescaled h1)
    k_agg_h<39, 40, 1><<<N / 8, 256>>>((const __half2*)hB, (__half2*)hA, N, b1);
    // layer 2 (aggregate-then-GEMM)
    k_agg_h<39, 40, 0><<<N / 8, 256>>>((const __half2*)hA, (__half2*)hB, N, nullptr);
    k_hmma<80, 5, 2, 2, 0><<<dim3(1, MH), 256, SM2>>>(hB, w2h, 156, hA, 160, N,
                                                      b2, nullptr, nullptr);
    // layer 3 (aggregate-then-GEMM, maxpool epilogue)
    k_agg_h<78, 80, 0><<<N / 8, 256>>>((const __half2*)hA, (__half2*)hB, N, nullptr);
    k_hmma<160, 5, 3, 2, 0><<<dim3(2, MH), 256, SM3>>>(hB, w3h, 312, nullptr, 0, N,
                                                       b3, batch, pool);

    // ---- graph head (fcg2 split-K x4 into pre-zeroed xc) ----
    k_gemm<1><<<dim3(4, 16), 256>>>((const float*)pool, 312, fcg1_w, 1024, S1, 1024,
                                    B, 1024, 312, fcg1_b, 312);
    k_gemm<4><<<dim3(4, 2, 4), 256>>>(S1, 1024, fcg2_w, 128, xc, 256,
                                      B, 128, 1024, fcg2_b, 256);

    // ---- protein branch (alphabet-factored conv) ----
    k_gbuild<<<B, 256>>>(target, conv_w);
    k_cconv<<<B, 256>>>(emb, conv_b);
    k_gemm<4><<<dim3(4, 2, 16), 256>>>(Cbuf, 3872, fcxt_w, 128, xc + 128, 256,
                                       B, 128, 3872, fcxt_b, 242);

    // ---- fusion head (fc2 split-K x4 into pre-zeroed S2, relu in k_out) ----
    k_gemm<1><<<dim3(4, 16), 256>>>(xc, 256, fc1_w, 1024, S1, 1024,
                                    B, 1024, 256, fc1_b, 256);
    k_gemm<4><<<dim3(4, 8, 4), 256>>>(S1, 1024, fc2_w, 512, S2, 512,
                                      B, 512, 1024, fc2_b, 256);
    k_out<<<(B + 7) / 8, 256>>>(out_w, out_b, out, B);
}

// round 14
// speedup vs baseline: 1.0229x; 1.0229x over previous
#include <cuda_runtime.h>
#include <cuda_fp16.h>
#include <cstdint>

// ---------------------------------------------------------------------------
// Problem constants (fixed by setup_inputs)
// ---------------------------------------------------------------------------
#define NN 250000
#define EE 1000000
#define BB 500
#define FD 78

// ---------------------------------------------------------------------------
// Scratch (device globals: no allocation allowed)
// ---------------------------------------------------------------------------
__device__ float    g_bufA[NN * 156];        // reused as fp16 (pitch 80/160)
__device__ float    g_bufB[NN * 156];
__device__ float    g_dinv[NN];
__device__ int      g_cnt[NN];
__device__ int      g_rowptr[NN + 1];
__device__ int      g_cursor[NN];
__device__ int      g_csrc[EE];
__device__ int      g_bsum[512];
__device__ int      g_boff[512];
__device__ unsigned g_pool[BB * 312];
__device__ float    g_S1[BB * 1024];
__device__ float    g_S1b[BB * 1024];
__device__ float    g_S2[BB * 512];
__device__ float    g_xc[BB * 256];
__device__ float    g_Cbuf[BB * 3872];
__device__ __half   g_W1h[78 * 80];          // W^T fp16, pitch-padded, pads zero
__device__ __half   g_W2h[156 * 80];
__device__ __half   g_W3h[312 * 160];

// ---------------------------------------------------------------------------
// mma / ldmatrix helpers (PTX ISA sm_80+, legal at compute_103)
// ---------------------------------------------------------------------------
__device__ __forceinline__ uint32_t smem_u32(const void* p) {
    uint32_t a;
    asm("{ .reg .u64 t; cvta.to.shared.u64 t, %1; cvt.u32.u64 %0, t; }" : "=r"(a) : "l"(p));
    return a;
}
__device__ __forceinline__ void ldm4(uint32_t* r, uint32_t addr) {
    asm volatile("ldmatrix.sync.aligned.m8n8.x4.shared.b16 {%0,%1,%2,%3}, [%4];"
        : "=r"(r[0]), "=r"(r[1]), "=r"(r[2]), "=r"(r[3]) : "r"(addr));
}
__device__ __forceinline__ void mma16816(float* c, const uint32_t* a, const uint32_t* b) {
    asm volatile(
        "mma.sync.aligned.m16n8k16.row.col.f32.f16.f16.f32 "
        "{%0,%1,%2,%3}, {%4,%5,%6,%7}, {%8,%9}, {%0,%1,%2,%3};"
        : "+f"(c[0]), "+f"(c[1]), "+f"(c[2]), "+f"(c[3])
        : "r"(a[0]), "r"(a[1]), "r"(a[2]), "r"(a[3]), "r"(b[0]), "r"(b[1]));
}

// ---------------------------------------------------------------------------
// Combined setup: zero cnt/pool/xc/S1/S1b/S2 + fp16-transpose W1/W2/W3.
// ---------------------------------------------------------------------------
#define SETUP_N0 (NN)                 // cnt
#define SETUP_N1 (BB * 312)           // pool
#define SETUP_N2 (BB * 256)           // xc
#define SETUP_N3 (BB * 512)           // S2
#define SETUP_N4 (BB * 1024)          // S1
#define SETUP_N5 (BB * 1024)          // S1b
#define SETUP_N6 (78 * 80)            // W1h
#define SETUP_N7 (156 * 80)           // W2h
#define SETUP_N8 (312 * 160)          // W3h
#define SETUP_TOT (SETUP_N0 + SETUP_N1 + SETUP_N2 + SETUP_N3 + SETUP_N4 + SETUP_N5 + SETUP_N6 + SETUP_N7 + SETUP_N8)

__global__ void k_setup(const float* __restrict__ W1, const float* __restrict__ W2,
                        const float* __restrict__ W3) {
    int i = blockIdx.x * blockDim.x + threadIdx.x;
    if (i < SETUP_N0) { g_cnt[i] = 0; return; }
    i -= SETUP_N0;
    if (i < SETUP_N1) { g_pool[i] = 0u; return; }
    i -= SETUP_N1;
    if (i < SETUP_N2) { g_xc[i] = 0.f; return; }
    i -= SETUP_N2;
    if (i < SETUP_N3) { g_S2[i] = 0.f; return; }
    i -= SETUP_N3;
    if (i < SETUP_N4) { g_S1[i] = 0.f; return; }
    i -= SETUP_N4;
    if (i < SETUP_N5) { g_S1b[i] = 0.f; return; }
    i -= SETUP_N5;
    if (i < SETUP_N6) {
        int m = i / 80, k = i - m * 80;
        g_W1h[i] = __float2half((k < 78) ? W1[(size_t)k * 78 + m] : 0.f);
        return;
    }
    i -= SETUP_N6;
    if (i < SETUP_N7) {
        int m = i / 80, k = i - m * 80;
        g_W2h[i] = __float2half((k < 78) ? W2[(size_t)k * 156 + m] : 0.f);
        return;
    }
    i -= SETUP_N7;
    if (i < SETUP_N8) {
        int m = i / 160, k = i - m * 160;
        g_W3h[i] = __float2half((k < 156) ? W3[(size_t)k * 312 + m] : 0.f);
    }
}

// ---------------------------------------------------------------------------
// CSR build: count -> scan -> offsets -> fill
// ---------------------------------------------------------------------------
__global__ void k_count(const int* __restrict__ dst, int e) {
    int i = blockIdx.x * blockDim.x + threadIdx.x;
    if (i < e) atomicAdd(&g_cnt[dst[i]], 1);
}

__global__ void k_scan1(int n) {
    __shared__ int s[512];
    int t = threadIdx.x;
    int i = blockIdx.x * 512 + t;
    int v = (i < n) ? g_cnt[i] : 0;
    s[t] = v;
    __syncthreads();
    for (int off = 1; off < 512; off <<= 1) {
        int tmp = (t >= off) ? s[t - off] : 0;
        __syncthreads();
        s[t] += tmp;
        __syncthreads();
    }
    if (i < n) g_rowptr[i] = s[t] - v;
    if (t == 511) g_bsum[blockIdx.x] = s[511];
}

__global__ void k_scan2(int nb) {
    __shared__ int s[512];
    int t = threadIdx.x;
    int v = (t < nb) ? g_bsum[t] : 0;
    s[t] = v;
    __syncthreads();
    for (int off = 1; off < 512; off <<= 1) {
        int tmp = (t >= off) ? s[t - off] : 0;
        __syncthreads();
        s[t] += tmp;
        __syncthreads();
    }
    if (t < nb) g_boff[t] = s[t] - v;
}

__global__ void k_scan3(int n, int e) {
    int i = blockIdx.x * blockDim.x + threadIdx.x;
    if (i < n) {
        int v = g_rowptr[i] + g_boff[i >> 9];
        g_rowptr[i] = v;
        g_cursor[i] = v;
        g_dinv[i] = rsqrtf((float)g_cnt[i] + 1.0f);
    }
    if (i == 0) g_rowptr[n] = e;
}

__global__ void k_fill(const int* __restrict__ src, const int* __restrict__ dst, int e) {
    int i = blockIdx.x * blockDim.x + threadIdx.x;
    if (i < e) {
        int d = dst[i];
        int p = atomicAdd(&g_cursor[d], 1);
        g_csrc[p] = src[i];
    }
}

// ---------------------------------------------------------------------------
// Aggregation kernels (one warp per node).
// k_agg0: fp32 input x, prescale both ends, fp16 output (pads zeroed)
// k_agg_h: fp16 prescaled input -> fp16 output
// ---------------------------------------------------------------------------
template <int F2, int P2>
__global__ void k_agg0(const float* __restrict__ in, __half2* __restrict__ out,
                       int n, int ldin) {
    int warp = (blockIdx.x * blockDim.x + threadIdx.x) >> 5;
    int lane = threadIdx.x & 31;
    if (warp >= n) return;
    const int v = warp;
    constexpr int R = (F2 + 31) / 32;
    float dv = g_dinv[v];
    float2 acc[R];
#pragma unroll
    for (int i = 0; i < R; i++) {
        int f2 = lane + 32 * i;
        if (f2 < F2) {
            acc[i].x = in[(size_t)v * ldin + 2 * f2] * dv;
            acc[i].y = in[(size_t)v * ldin + 2 * f2 + 1] * dv;
        } else acc[i] = make_float2(0.f, 0.f);
    }
    int e0 = g_rowptr[v], e1 = g_rowptr[v + 1];
    for (int e = e0; e < e1; e++) {
        int u = g_csrc[e];
        float us = g_dinv[u];
#pragma unroll
        for (int i = 0; i < R; i++) {
            int f2 = lane + 32 * i;
            if (f2 < F2) {
                acc[i].x += in[(size_t)u * ldin + 2 * f2] * us;
                acc[i].y += in[(size_t)u * ldin + 2 * f2 + 1] * us;
            }
        }
    }
#pragma unroll
    for (int i = 0; i < R; i++) {
        int f2 = lane + 32 * i;
        if (f2 < F2)
            out[(size_t)v * P2 + f2] = __floats2half2_rn(acc[i].x * dv, acc[i].y * dv);
        else if (f2 < P2)
            out[(size_t)v * P2 + f2] = __floats2half2_rn(0.f, 0.f);
    }
}

template <int F2, int P2>
__global__ void k_agg_h(const __half2* __restrict__ in, __half2* __restrict__ out, int n) {
    int warp = (blockIdx.x * blockDim.x + threadIdx.x) >> 5;
    int lane = threadIdx.x & 31;
    if (warp >= n) return;
    const int v = warp;
    constexpr int R = (F2 + 31) / 32;
    float dv = g_dinv[v];
    float2 acc[R];
#pragma unroll
    for (int i = 0; i < R; i++) {
        int f2 = lane + 32 * i;
        acc[i] = (f2 < F2) ? __half22float2(in[(size_t)v * P2 + f2]) : make_float2(0.f, 0.f);
    }
    int e0 = g_rowptr[v], e1 = g_rowptr[v + 1];
    for (int e = e0; e < e1; e++) {
        int u = g_csrc[e];
#pragma unroll
        for (int i = 0; i < R; i++) {
            int f2 = lane + 32 * i;
            if (f2 < F2) {
                float2 t = __half22float2(in[(size_t)u * P2 + f2]);
                acc[i].x += t.x;
                acc[i].y += t.y;
            }
        }
    }
#pragma unroll
    for (int i = 0; i < R; i++) {
        int f2 = lane + 32 * i;
        if (f2 < F2)
            out[(size_t)v * P2 + f2] = __floats2half2_rn(acc[i].x * dv, acc[i].y * dv);
        else if (f2 < P2)
            out[(size_t)v * P2 + f2] = __floats2half2_rn(0.f, 0.f);
    }
}

// ---------------------------------------------------------------------------
// fp16 HMMA GEMM: C[node, feat] = X[node, :] @ Wt^T, fp32 accum.
// X fp16 pitch KTILE (pads zeroed); Wt fp16 [Mout][KTILE] pitch KTILE.
// Block tile 128 x BN (BN = NT2*32). MINB = min blocks/SM.
// EPI 2: C = half(relu(acc+bias)*dinv[node]); EPI 3: maxpool atomicMax.
// ---------------------------------------------------------------------------
template <int KTILE, int NT2, int EPI, int MINB>
__global__ __launch_bounds__(256, MINB)
void k_hmma(const __half* __restrict__ X,
            const __half* __restrict__ Wt, int Mout,
            __half* __restrict__ C, int ldc,
            int NR,
            const float* __restrict__ bias,
            const int* __restrict__ batch,
            unsigned* __restrict__ pool) {
    constexpr int PA = KTILE + 8;
    constexpr int KS = KTILE / 16;
    constexpr int CW = KTILE / 8;
    constexpr int BN = NT2 * 32;
    constexpr int NT = 2 * NT2;
    extern __shared__ __half sm[];
    __half* Asm = sm;                       // [128][PA]
    __half* Bsm = sm + 128 * PA;            // [BN][PA]

    const int tid = threadIdx.x;
    const int wid = tid >> 5;
    const int lane = tid & 31;
    const int n0 = blockIdx.x * BN;
    const int m0 = blockIdx.y * 128;
    const int wm = (wid & 3) * 32;
    const int wn = (wid >> 2) * (NT2 * 16);
    const int g = lane >> 2, tg = lane & 3;
    const int r8 = lane & 7, q = lane >> 3;

#pragma unroll 4
    for (int idx = tid; idx < 128 * CW; idx += 256) {
        int row = idx / CW;
        int c = idx - row * CW;
        int node = m0 + row;
        uint4 v = make_uint4(0u, 0u, 0u, 0u);
        if (node < NR) v = *(const uint4*)&X[(size_t)node * KTILE + c * 8];
        *(uint4*)&Asm[row * PA + c * 8] = v;
    }
#pragma unroll 4
    for (int idx = tid; idx < BN * CW; idx += 256) {
        int row = idx / CW;
        int c = idx - row * CW;
        int feat = n0 + row;
        uint4 v = make_uint4(0u, 0u, 0u, 0u);
        if (feat < Mout) v = *(const uint4*)&Wt[(size_t)feat * KTILE + c * 8];
        *(uint4*)&Bsm[row * PA + c * 8] = v;
    }
    __syncthreads();

    const uint32_t sA = smem_u32(Asm);
    const uint32_t sB = smem_u32(Bsm);

    uint32_t aAddr[2], bAddr[NT2];
#pragma unroll
    for (int mt = 0; mt < 2; mt++)
        aAddr[mt] = sA + (uint32_t)((wm + mt * 16 + r8 + (q & 1) * 8) * PA + (q >> 1) * 8) * 2;
#pragma unroll
    for (int h = 0; h < NT2; h++)
        bAddr[h] = sB + (uint32_t)((wn + h * 16 + r8 + (q >> 1) * 8) * PA + (q & 1) * 8) * 2;

    float acc[2][NT][4];
#pragma unroll
    for (int mt = 0; mt < 2; mt++)
#pragma unroll
        for (int nt = 0; nt < NT; nt++)
#pragma unroll
            for (int i = 0; i < 4; i++) acc[mt][nt][i] = 0.f;

#pragma unroll
    for (int ks = 0; ks < KS; ks++) {
        uint32_t a[2][4], b[NT2][4];
        ldm4(a[0], aAddr[0] + ks * 32u);
        ldm4(a[1], aAddr[1] + ks * 32u);
#pragma unroll
        for (int h = 0; h < NT2; h++)
            ldm4(b[h], bAddr[h] + ks * 32u);
#pragma unroll
        for (int mt = 0; mt < 2; mt++)
#pragma unroll
            for (int nt = 0; nt < NT; nt++)
                mma16816(acc[mt][nt], a[mt], &b[nt >> 1][(nt & 1) * 2]);
    }

    if (EPI == 2) {
#pragma unroll
        for (int mt = 0; mt < 2; mt++) {
#pragma unroll
            for (int h = 0; h < 2; h++) {
                int node = m0 + wm + mt * 16 + g + h * 8;
                if (node >= NR) continue;
                float dv = g_dinv[node];
#pragma unroll
                for (int nt = 0; nt < NT; nt++) {
                    int feat = n0 + wn + nt * 8 + 2 * tg;
                    if (feat >= Mout) continue;
                    float ox = fmaxf(acc[mt][nt][h * 2 + 0] + bias[feat], 0.f) * dv;
                    float oy = fmaxf(acc[mt][nt][h * 2 + 1] + bias[feat + 1], 0.f) * dv;
                    *(__half2*)&C[(size_t)node * ldc + feat] = __floats2half2_rn(ox, oy);
                }
            }
        }
    } else {
        int nodeA = m0 + wm + g;
        bool allv = (nodeA + 24) < NR;
        bool samegraph = allv && (batch[nodeA] == batch[nodeA + 24]);
        if (samegraph) {
            int bg = batch[nodeA];
#pragma unroll
            for (int nt = 0; nt < NT; nt++) {
                int feat = n0 + wn + nt * 8 + 2 * tg;
                if (feat >= Mout) continue;
#pragma unroll
                for (int e = 0; e < 2; e++) {
                    float m = fmaxf(fmaxf(acc[0][nt][e], acc[0][nt][2 + e]),
                                    fmaxf(acc[1][nt][e], acc[1][nt][2 + e]));
                    float v = fmaxf(m + bias[feat + e], 0.f);
                    if (v > 0.f)
                        atomicMax(&pool[(size_t)bg * 312 + feat + e], __float_as_uint(v));
                }
            }
        } else {
#pragma unroll
            for (int mt = 0; mt < 2; mt++) {
#pragma unroll
                for (int h = 0; h < 2; h++) {
                    int node = m0 + wm + mt * 16 + g + h * 8;
                    if (node >= NR) continue;
                    int bg = batch[node];
#pragma unroll
                    for (int nt = 0; nt < NT; nt++) {
                        int feat = n0 + wn + nt * 8 + 2 * tg;
                        if (feat >= Mout) continue;
#pragma unroll
                        for (int e = 0; e < 2; e++) {
                            float v = fmaxf(acc[mt][nt][h * 2 + e] + bias[feat + e], 0.f);
                            if (v > 0.f)
                                atomicMax(&pool[(size_t)bg * 312 + feat + e], __float_as_uint(v));
                        }
                    }
                }
            }
        }
    }
}

// ---------------------------------------------------------------------------
// Scalar f32 SIMT GEMM (small head GEMMs): C[NR,M] = A[NR,K] @ W[K,M]
// EPI: 0 STORE, 1 RELU, 4 ADD_ATOMIC (split-K, bias on z==0)
// RELUA: apply relu to A elements on load (deferred producer relu)
// ---------------------------------------------------------------------------
#define GBM 128
#define GBN 64
#define GBK 16

template <int EPI, int RELUA>
__global__ __launch_bounds__(256)
void k_gemm(const float* __restrict__ A, int lda,
            const float* __restrict__ W, int ldb,
            float* __restrict__ C, int ldc,
            int NR, int M, int K,
            const float* __restrict__ bias,
            int kChunk) {
    __shared__ float As[GBK][GBM + 4];
    __shared__ float Bs[GBK][GBN + 4];

    const int m0 = blockIdx.x * GBM;
    const int n0 = blockIdx.y * GBN;
    const int kb = blockIdx.z * kChunk;
    const int ke = min(K, kb + kChunk);

    const int tid = threadIdx.x;
    const int tN = tid & 15;
    const int tM = tid >> 4;

    float acc[8][4];
#pragma unroll
    for (int i = 0; i < 8; i++)
#pragma unroll
        for (int j = 0; j < 4; j++) acc[i][j] = 0.f;

    for (int k0 = kb; k0 < ke; k0 += GBK) {
#pragma unroll
        for (int r = 0; r < 8; r++) {
            int idx = tid + r * 256;
            int mm = idx >> 4, kk = idx & 15;
            int gm = m0 + mm, gk = k0 + kk;
            float v = (gm < NR && gk < ke) ? A[(size_t)gm * lda + gk] : 0.f;
            As[kk][mm] = RELUA ? fmaxf(v, 0.f) : v;
        }
#pragma unroll
        for (int r = 0; r < 4; r++) {
            int idx = tid + r * 256;
            int kk = idx >> 6, nn = idx & 63;
            int gk = k0 + kk, gn = n0 + nn;
            Bs[kk][nn] = (gk < ke && gn < M) ? W[(size_t)gk * ldb + gn] : 0.f;
        }
        __syncthreads();
#pragma unroll
        for (int kk = 0; kk < GBK; kk++) {
            float4 a0 = *reinterpret_cast<const float4*>(&As[kk][tM * 8]);
            float4 a1 = *reinterpret_cast<const float4*>(&As[kk][tM * 8 + 4]);
            float4 b0 = *reinterpret_cast<const float4*>(&Bs[kk][tN * 4]);
            float a[8] = {a0.x, a0.y, a0.z, a0.w, a1.x, a1.y, a1.z, a1.w};
            float b[4] = {b0.x, b0.y, b0.z, b0.w};
#pragma unroll
            for (int i = 0; i < 8; i++)
#pragma unroll
                for (int j = 0; j < 4; j++)
                    acc[i][j] = fmaf(a[i], b[j], acc[i][j]);
        }
        __syncthreads();
    }

#pragma unroll
    for (int i = 0; i < 8; i++) {
        int row = m0 + tM * 8 + i;
        if (row >= NR) continue;
#pragma unroll
        for (int j = 0; j < 4; j++) {
            int col = n0 + tN * 4 + j;
            if (col >= M) continue;
            float v = acc[i][j];
            if (EPI == 0) {
                if (bias) v += bias[col];
                C[(size_t)row * ldc + col] = v;
            } else if (EPI == 1) {
                v += bias[col];
                C[(size_t)row * ldc + col] = fmaxf(v, 0.f);
            } else {  // 4
                if (blockIdx.z == 0 && bias) v += bias[col];
                atomicAdd(&C[(size_t)row * ldc + col], v);
            }
        }
    }
}

// ---------------------------------------------------------------------------
// Fused protein branch: per-graph b,
//   G[o,k,l] = sum_i conv_w[o,i,k] * [target[b,i]==l]      (in smem)
//   Cbuf[b,o,h] = conv_b[o] + sum_{k,l} G[o,k,l] * emb[l,h+k]
// G never leaves shared memory. Dynamic smem: ts 1024i + accG 6656f +
// GsT 6864f + Es 3744f = 73152 B.
// ---------------------------------------------------------------------------
__global__ void k_prot(const int* __restrict__ target, const float* __restrict__ conv_w,
                       const float* __restrict__ emb, const float* __restrict__ conv_b) {
    extern __shared__ float sp[];
    int*   ts   = (int*)sp;                 // [1024]
    float* accG = sp + 1024;                // [6656]  [(o*8+k)*26 + l]
    float* GsT  = sp + 1024 + 6656;         // [6864]  [(k*26+l)*33 + o]
    float* Es   = GsT + 6864;               // [3744]  [l*144 + c], tail zero
    const int b = blockIdx.x, tid = threadIdx.x;

    for (int i = tid; i < 1000; i += 256) ts[i] = target[b * 1000 + i];
#pragma unroll
    for (int l = 0; l < 26; l++) accG[tid * 26 + l] = 0.f;
    for (int i = tid; i < 26 * 144; i += 256) {
        int l = i / 144, c = i - l * 144;
        Es[i] = (c < 128) ? emb[l * 128 + c] : 0.f;
    }
    __syncthreads();

    {   // gbuild phase: thread = (o,k)
        const int o = tid >> 3, k = tid & 7;
        const float* wp = conv_w + o * 8000 + k;
        for (int i = 0; i < 1000; i++)
            accG[tid * 26 + ts[i]] += wp[i * 8];
    }
    __syncthreads();

    // transpose accG -> GsT (conflict-free o-broadcast layout)
    for (int i = tid; i < 6656; i += 256) {
        int o = i / 208;
        int r = i - o * 208;
        int k = r / 26;
        int l = r - k * 26;
        GsT[(k * 26 + l) * 33 + o] = accG[i];
    }
    __syncthreads();

    // cconv phase: 512 tasks = 16 h-groups x 32 o
#pragma unroll
    for (int t2 = 0; t2 < 2; t2++) {
        int task = tid + t2 * 256;
        int o = task & 31;
        int hg = task >> 5;
        int h0 = hg * 8;
        float cb = conv_b[o];
        float acc[8];
#pragma unroll
        for (int j = 0; j < 8; j++) acc[j] = cb;
        for (int l = 0; l < 26; l++) {
            float e[15];
#pragma unroll
            for (int t = 0; t < 15; t++) e[t] = Es[l * 144 + h0 + t];
#pragma unroll
            for (int k = 0; k < 8; k++) {
                float gv = GsT[(k * 26 + l) * 33 + o];
#pragma unroll
                for (int j = 0; j < 8; j++)
                    acc[j] = fmaf(gv, e[j + k], acc[j]);
            }
        }
#pragma unroll
        for (int j = 0; j < 8; j++) {
            int h = h0 + j;
            if (h < 121) g_Cbuf[(size_t)b * 3872 + o * 121 + h] = acc[j];
        }
    }
}

// ---------------------------------------------------------------------------
// Final projection: out[r] = dot(relu(S2[r,:512]), out_w) + out_b.
// ---------------------------------------------------------------------------
__global__ void k_out(const float* __restrict__ ow, const float* __restrict__ ob,
                      float* __restrict__ out, int rows) {
    int row = blockIdx.x * 8 + (threadIdx.x >> 5);
    int lane = threadIdx.x & 31;
    if (row >= rows) return;
    float s = 0.f;
    for (int j = lane; j < 512; j += 32) s += fmaxf(g_S2[row * 512 + j], 0.f) * ow[j];
#pragma unroll
    for (int off = 16; off; off >>= 1) s += __shfl_down_sync(0xffffffffu, s, off);
    if (lane == 0) out[row] = s + ob[0];
}

// ---------------------------------------------------------------------------
// Launch
// ---------------------------------------------------------------------------
extern "C" void kernel_launch(void* const* d_in, const int* in_sizes, int n_in,
                              void* d_out, int out_size) {
    const float* x       = (const float*)d_in[0];
    const int*   ei      = (const int*)d_in[1];
    const int*   batch   = (const int*)d_in[2];
    const int*   target  = (const int*)d_in[3];
    const float* W1      = (const float*)d_in[4];
    const float* b1      = (const float*)d_in[5];
    const float* W2      = (const float*)d_in[6];
    const float* b2      = (const float*)d_in[7];
    const float* W3      = (const float*)d_in[8];
    const float* b3      = (const float*)d_in[9];
    const float* fcg1_w  = (const float*)d_in[10];
    const float* fcg1_b  = (const float*)d_in[11];
    const float* fcg2_w  = (const float*)d_in[12];
    const float* fcg2_b  = (const float*)d_in[13];
    const float* emb     = (const float*)d_in[14];
    const float* conv_w  = (const float*)d_in[15];
    const float* conv_b  = (const float*)d_in[16];
    const float* fcxt_w  = (const float*)d_in[17];
    const float* fcxt_b  = (const float*)d_in[18];
    const float* fc1_w   = (const float*)d_in[19];
    const float* fc1_b   = (const float*)d_in[20];
    const float* fc2_w   = (const float*)d_in[21];
    const float* fc2_b   = (const float*)d_in[22];
    const float* out_w   = (const float*)d_in[23];
    const float* out_b   = (const float*)d_in[24];
    float* out = (float*)d_out;

    float *bufA, *bufB, *S1, *S1b, *S2, *xc, *Cbuf;
    __half *w1h, *w2h, *w3h;
    unsigned* pool;
    cudaGetSymbolAddress((void**)&bufA, g_bufA);
    cudaGetSymbolAddress((void**)&bufB, g_bufB);
    cudaGetSymbolAddress((void**)&pool, g_pool);
    cudaGetSymbolAddress((void**)&S1,   g_S1);
    cudaGetSymbolAddress((void**)&S1b,  g_S1b);
    cudaGetSymbolAddress((void**)&S2,   g_S2);
    cudaGetSymbolAddress((void**)&xc,   g_xc);
    cudaGetSymbolAddress((void**)&Cbuf, g_Cbuf);
    cudaGetSymbolAddress((void**)&w1h,  g_W1h);
    cudaGetSymbolAddress((void**)&w2h,  g_W2h);
    cudaGetSymbolAddress((void**)&w3h,  g_W3h);

    __half* hA = (__half*)bufA;
    __half* hB = (__half*)bufB;

    const int N = NN, E = EE, B = BB;
    const int NB = (N + 511) / 512;
    const int MH = (N + 127) / 128;

    const int SM1 = (128 + 96) * 88 * 2;          // 39424 (KTILE=80,  BN=96)
    const int SM2 = (128 + 160) * 88 * 2;         // 50688 (KTILE=80,  BN=160)
    const int SM3 = (128 + 160) * 168 * 2;        // 96768 (KTILE=160, BN=160)
    const int SMP = (1024 + 6656 + 6864 + 3744) * 4;  // 73152 (k_prot)
    cudaFuncSetAttribute(k_hmma<80, 3, 2, 2>,  cudaFuncAttributeMaxDynamicSharedMemorySize, SM1);
    cudaFuncSetAttribute(k_hmma<80, 5, 2, 2>,  cudaFuncAttributeMaxDynamicSharedMemorySize, SM2);
    cudaFuncSetAttribute(k_hmma<160, 5, 3, 2>, cudaFuncAttributeMaxDynamicSharedMemorySize, SM3);
    cudaFuncSetAttribute(k_prot, cudaFuncAttributeMaxDynamicSharedMemorySize, SMP);

    // ---- combined setup (zeros + W-preps) ----
    k_setup<<<(SETUP_TOT + 255) / 256, 256>>>(W1, W2, W3);

    // ---- CSR + dinv ----
    k_count<<<(E + 255) / 256, 256>>>(ei + E, E);
    k_scan1<<<NB, 512>>>(N);
    k_scan2<<<1, 512>>>(NB);
    k_scan3<<<(N + 255) / 256, 256>>>(N, E);
    k_fill<<<(E + 255) / 256, 256>>>(ei, ei + E, E);

    // ---- GCN layers (R12-proven order: aggregate-then-GEMM) ----
    k_agg0<39, 40><<<N / 8, 256>>>(x, (__half2*)hA, N, 78);
    k_hmma<80, 3, 2, 2><<<dim3(1, MH), 256, SM1>>>(hA, w1h, 78, hB, 80, N,
                                                   b1, nullptr, nullptr);
    k_agg_h<39, 40><<<N / 8, 256>>>((const __half2*)hB, (__half2*)hA, N);
    k_hmma<80, 5, 2, 2><<<dim3(1, MH), 256, SM2>>>(hA, w2h, 156, hB, 160, N,
                                                   b2, nullptr, nullptr);
    k_agg_h<78, 80><<<N / 8, 256>>>((const __half2*)hB, (__half2*)hA, N);
    k_hmma<160, 5, 3, 2><<<dim3(2, MH), 256, SM3>>>(hA, w3h, 312, nullptr, 0, N,
                                                    b3, batch, pool);

    // ---- graph head: fcg1 split-K x4 (no relu) -> fcg2 reads relu(S1) ----
    k_gemm<4, 0><<<dim3(4, 16, 4), 256>>>((const float*)pool, 312, fcg1_w, 1024, S1, 1024,
                                          B, 1024, 312, fcg1_b, 78);
    k_gemm<4, 1><<<dim3(4, 2, 4), 256>>>(S1, 1024, fcg2_w, 128, xc, 256,
                                         B, 128, 1024, fcg2_b, 256);

    // ---- protein branch (fused gbuild+cconv) ----
    k_prot<<<B, 256, SMP>>>(target, conv_w, emb, conv_b);
    k_gemm<4, 0><<<dim3(4, 2, 16), 256>>>(Cbuf, 3872, fcxt_w, 128, xc + 128, 256,
                                          B, 128, 3872, fcxt_b, 242);

    // ---- fusion head: fc1 split-K x4 -> fc2 reads relu(S1b); relu in k_out ----
    k_gemm<4, 0><<<dim3(4, 16, 4), 256>>>(xc, 256, fc1_w, 1024, S1b, 1024,
                                          B, 1024, 256, fc1_b, 64);
    k_gemm<4, 1><<<dim3(4, 8, 4), 256>>>(S1b, 1024, fc2_w, 512, S2, 512,
                                         B, 512, 1024, fc2_b, 256);
    k_out<<<(B + 7) / 8, 256>>>(out_w, out_b, out, B);
}